// round 1
// baseline (speedup 1.0000x reference)
#include <cuda_runtime.h>
#include <cstdint>

#define N_NODES 200000
#define MAX_E   6400000

// Scratch (static __device__ — no allocations allowed)
__device__ float4   g_acc1[N_NODES * 4];   // 16 floats/node: msg[0..10], deg at [11], pad
__device__ float4   g_h1  [N_NODES * 8];   // 32 floats/node
__device__ float4   g_acc2[N_NODES * 8];   // 32 floats/node
__device__ unsigned g_gmax[32];

__device__ __forceinline__ void red_v4(float* p, float a, float b, float c, float d) {
    asm volatile("red.global.add.v4.f32 [%0], {%1,%2,%3,%4};"
                 :: "l"(p), "f"(a), "f"(b), "f"(c), "f"(d) : "memory");
}

__device__ __forceinline__ float sigmoidf_(float x) {
    return 1.0f / (1.0f + __expf(-x));
}

// ---------------------------------------------------------------- init
__global__ void k_init() {
    int i = blockIdx.x * blockDim.x + threadIdx.x;
    float4 z = make_float4(0.f, 0.f, 0.f, 0.f);
    if (i < N_NODES * 4) g_acc1[i] = z;
    if (i < N_NODES * 8) g_acc2[i] = z;
    if (i < 32)          g_gmax[i] = 0u;   // bits of 0.0f; outputs are post-ReLU (>=0)
}

// ---------------------------------------------------------------- layer-1 edge scatter
// msg1 = sigmoid(mask[e/2]) * [edge_feat(4) | node_feat[src](7)], plus deg count.
__global__ void k_edge1(const float* __restrict__ nf, const float* __restrict__ ef,
                        const float* __restrict__ mask,
                        const int* __restrict__ src, const int* __restrict__ dst, int E) {
    int e = blockIdx.x * blockDim.x + threadIdx.x;
    if (e >= E) return;
    float m = sigmoidf_(__ldg(mask + (e >> 1)));
    float4 f = __ldg(((const float4*)ef) + e);
    int s = src[e];
    int d = dst[e];
    const float* np = nf + (size_t)s * 7;
    float n0 = __ldg(np + 0), n1 = __ldg(np + 1), n2 = __ldg(np + 2), n3 = __ldg(np + 3);
    float n4 = __ldg(np + 4), n5 = __ldg(np + 5), n6 = __ldg(np + 6);
    float* base = (float*)(g_acc1 + (size_t)d * 4);
    red_v4(base + 0, m * f.x, m * f.y, m * f.z, m * f.w);
    red_v4(base + 4, m * n0,  m * n1,  m * n2,  m * n3);
    red_v4(base + 8, m * n4,  m * n5,  m * n6,  1.0f);   // last lane accumulates degree
}

// ---------------------------------------------------------------- layer-1 MLP
__global__ void __launch_bounds__(256)
k_mlp1(const float* __restrict__ W1a, const float* __restrict__ b1a,
       const float* __restrict__ W1b, const float* __restrict__ b1b) {
    __shared__ float sWa[11 * 32], sba[32], sWb[32 * 32], sbb[32];
    for (int i = threadIdx.x; i < 11 * 32; i += blockDim.x) sWa[i] = W1a[i];
    for (int i = threadIdx.x; i < 32 * 32; i += blockDim.x) sWb[i] = W1b[i];
    if (threadIdx.x < 32) { sba[threadIdx.x] = b1a[threadIdx.x]; sbb[threadIdx.x] = b1b[threadIdx.x]; }
    __syncthreads();

    int v = blockIdx.x * blockDim.x + threadIdx.x;
    if (v >= N_NODES) return;
    const float4* ap = g_acc1 + (size_t)v * 4;
    float4 r0 = ap[0], r1 = ap[1], r2 = ap[2];
    float inv = 1.0f / fmaxf(r2.w, 1.0f);   // r2.w = degree
    float x[11] = { r0.x * inv, r0.y * inv, r0.z * inv, r0.w * inv,
                    r1.x * inv, r1.y * inv, r1.z * inv, r1.w * inv,
                    r2.x * inv, r2.y * inv, r2.z * inv };
    float h[32];
#pragma unroll
    for (int j = 0; j < 32; j++) {
        float s = sba[j];
#pragma unroll
        for (int k = 0; k < 11; k++) s += x[k] * sWa[k * 32 + j];
        h[j] = fmaxf(s, 0.f);
    }
    float4* op = g_h1 + (size_t)v * 8;
#pragma unroll
    for (int q = 0; q < 8; q++) {
        float o[4];
#pragma unroll
        for (int jj = 0; jj < 4; jj++) {
            int j = q * 4 + jj;
            float s = sbb[j];
#pragma unroll
            for (int k = 0; k < 32; k++) s += h[k] * sWb[k * 32 + j];
            o[jj] = fmaxf(s, 0.f);
        }
        op[q] = make_float4(o[0], o[1], o[2], o[3]);
    }
}

// ---------------------------------------------------------------- layer-2 edge scatter
__global__ void k_edge2(const float* __restrict__ mask,
                        const int* __restrict__ src, const int* __restrict__ dst, int E) {
    int e = blockIdx.x * blockDim.x + threadIdx.x;
    if (e >= E) return;
    float m = sigmoidf_(__ldg(mask + (e >> 1)));
    int s = src[e];
    int d = dst[e];
    const float4* hp = g_h1 + (size_t)s * 8;
    float* base = (float*)(g_acc2 + (size_t)d * 8);
#pragma unroll
    for (int q = 0; q < 8; q++) {
        float4 h = __ldg(hp + q);
        red_v4(base + q * 4, m * h.x, m * h.y, m * h.z, m * h.w);
    }
}

// ---------------------------------------------------------------- layer-2 MLP + block max
__global__ void __launch_bounds__(256)
k_mlp2max(const float* __restrict__ W2a, const float* __restrict__ b2a,
          const float* __restrict__ W2b, const float* __restrict__ b2b) {
    __shared__ float sWa[32 * 32], sba[32], sWb[32 * 32], sbb[32];
    __shared__ float sred[8 * 32];
    for (int i = threadIdx.x; i < 32 * 32; i += blockDim.x) { sWa[i] = W2a[i]; sWb[i] = W2b[i]; }
    if (threadIdx.x < 32) { sba[threadIdx.x] = b2a[threadIdx.x]; sbb[threadIdx.x] = b2b[threadIdx.x]; }
    __syncthreads();

    float lmax[32];
#pragma unroll
    for (int j = 0; j < 32; j++) lmax[j] = 0.f;

    int stride = gridDim.x * blockDim.x;
    for (int v = blockIdx.x * blockDim.x + threadIdx.x; v < N_NODES; v += stride) {
        float deg = ((const float*)(g_acc1 + (size_t)v * 4))[11];
        float inv = 1.0f / fmaxf(deg, 1.0f);
        const float4* ap = g_acc2 + (size_t)v * 8;
        float x[32];
#pragma unroll
        for (int q = 0; q < 8; q++) {
            float4 r = ap[q];
            x[q * 4 + 0] = r.x * inv; x[q * 4 + 1] = r.y * inv;
            x[q * 4 + 2] = r.z * inv; x[q * 4 + 3] = r.w * inv;
        }
        float h[32];
#pragma unroll
        for (int j = 0; j < 32; j++) {
            float s = sba[j];
#pragma unroll
            for (int k = 0; k < 32; k++) s += x[k] * sWa[k * 32 + j];
            h[j] = fmaxf(s, 0.f);
        }
#pragma unroll
        for (int j = 0; j < 32; j++) {
            float s = sbb[j];
#pragma unroll
            for (int k = 0; k < 32; k++) s += h[k] * sWb[k * 32 + j];
            lmax[j] = fmaxf(lmax[j], fmaxf(s, 0.f));
        }
    }

    // warp butterfly reduce (all lanes end with the warp max vector)
#pragma unroll
    for (int off = 16; off; off >>= 1)
#pragma unroll
        for (int j = 0; j < 32; j++)
            lmax[j] = fmaxf(lmax[j], __shfl_xor_sync(0xFFFFFFFFu, lmax[j], off));

    int warp = threadIdx.x >> 5, lane = threadIdx.x & 31;
    sred[warp * 32 + lane] = lmax[lane];
    __syncthreads();
    if (threadIdx.x < 32) {
        float mv = sred[threadIdx.x];
        int nw = blockDim.x >> 5;
        for (int w = 1; w < nw; w++) mv = fmaxf(mv, sred[w * 32 + threadIdx.x]);
        atomicMax(&g_gmax[threadIdx.x], __float_as_uint(mv));  // valid: all values >= 0
    }
}

// ---------------------------------------------------------------- readout
__global__ void k_final(const float* __restrict__ Wm1, const float* __restrict__ bm1,
                        const float* __restrict__ Wm2, const float* __restrict__ bm2,
                        float* __restrict__ out) {
    __shared__ float sg[32], sh[16];
    int t = threadIdx.x;
    sg[t] = __uint_as_float(g_gmax[t]);
    __syncwarp();
    if (t < 16) {
        float s = bm1[t];
#pragma unroll
        for (int k = 0; k < 32; k++) s += sg[k] * Wm1[k * 16 + t];
        sh[t] = fmaxf(s, 0.f);
    }
    __syncwarp();
    if (t == 0) {
        float l0 = bm2[0], l1 = bm2[1];
#pragma unroll
        for (int k = 0; k < 16; k++) { l0 += sh[k] * Wm2[k * 2 + 0]; l1 += sh[k] * Wm2[k * 2 + 1]; }
        float mx = fmaxf(l0, l1);
        float e0 = __expf(l0 - mx), e1 = __expf(l1 - mx);
        float inv = 1.f / (e0 + e1);
        out[0] = e0 * inv;
        out[1] = e1 * inv;
    }
}

// ---------------------------------------------------------------- launch
extern "C" void kernel_launch(void* const* d_in, const int* in_sizes, int n_in,
                              void* d_out, int out_size) {
    const float* node_feat = (const float*)d_in[0];
    const float* edge_feat = (const float*)d_in[1];
    const float* edge_mask = (const float*)d_in[2];
    const int*   src       = (const int*)  d_in[3];
    const int*   dst       = (const int*)  d_in[4];
    const float* W1a = (const float*)d_in[5];
    const float* b1a = (const float*)d_in[6];
    const float* W1b = (const float*)d_in[7];
    const float* b1b = (const float*)d_in[8];
    const float* W2a = (const float*)d_in[9];
    const float* b2a = (const float*)d_in[10];
    const float* W2b = (const float*)d_in[11];
    const float* b2b = (const float*)d_in[12];
    const float* Wm1 = (const float*)d_in[13];
    const float* bm1 = (const float*)d_in[14];
    const float* Wm2 = (const float*)d_in[15];
    const float* bm2 = (const float*)d_in[16];
    float* out = (float*)d_out;

    int E = in_sizes[3];

    k_init<<<(N_NODES * 8 + 255) / 256, 256>>>();
    k_edge1<<<(E + 255) / 256, 256>>>(node_feat, edge_feat, edge_mask, src, dst, E);
    k_mlp1<<<(N_NODES + 255) / 256, 256>>>(W1a, b1a, W1b, b1b);
    k_edge2<<<(E + 255) / 256, 256>>>(edge_mask, src, dst, E);
    k_mlp2max<<<592, 256>>>(W2a, b2a, W2b, b2b);
    k_final<<<1, 32>>>(Wm1, bm1, Wm2, bm2, out);
}

// round 2
// speedup vs baseline: 1.0003x; 1.0003x over previous
#include <cuda_runtime.h>
#include <cstdint>

#define N_NODES 200000
#define MAX_E   6400000

// Scratch (static __device__ — no allocations allowed)
__device__ float4   g_acc1[N_NODES * 4];   // 16 floats/node: msg[0..10], deg at [11], pad
__device__ float4   g_h1  [N_NODES * 8];   // 32 floats/node
__device__ float4   g_acc2[N_NODES * 8];   // 32 floats/node
__device__ unsigned g_gmax[32];

__device__ __forceinline__ void red_v4(float* p, float a, float b, float c, float d) {
    asm volatile("red.global.add.v4.f32 [%0], {%1,%2,%3,%4};"
                 :: "l"(p), "f"(a), "f"(b), "f"(c), "f"(d) : "memory");
}

__device__ __forceinline__ float sigmoidf_(float x) {
    return 1.0f / (1.0f + __expf(-x));
}

// ---------------------------------------------------------------- init
__global__ void k_init() {
    int i = blockIdx.x * blockDim.x + threadIdx.x;
    float4 z = make_float4(0.f, 0.f, 0.f, 0.f);
    if (i < N_NODES * 4) g_acc1[i] = z;
    if (i < N_NODES * 8) g_acc2[i] = z;
    if (i < 32)          g_gmax[i] = 0u;   // bits of 0.0f; outputs are post-ReLU (>=0)
}

// ---------------------------------------------------------------- layer-1 edge scatter
// msg1 = sigmoid(mask[e/2]) * [edge_feat(4) | node_feat[src](7)], plus deg count.
__global__ void k_edge1(const float* __restrict__ nf, const float* __restrict__ ef,
                        const float* __restrict__ mask,
                        const int* __restrict__ src, const int* __restrict__ dst, int E) {
    int e = blockIdx.x * blockDim.x + threadIdx.x;
    if (e >= E) return;
    float m = sigmoidf_(__ldg(mask + (e >> 1)));
    float4 f = __ldg(((const float4*)ef) + e);
    int s = src[e];
    int d = dst[e];
    const float* np = nf + (size_t)s * 7;
    float n0 = __ldg(np + 0), n1 = __ldg(np + 1), n2 = __ldg(np + 2), n3 = __ldg(np + 3);
    float n4 = __ldg(np + 4), n5 = __ldg(np + 5), n6 = __ldg(np + 6);
    float* base = (float*)(g_acc1 + (size_t)d * 4);
    red_v4(base + 0, m * f.x, m * f.y, m * f.z, m * f.w);
    red_v4(base + 4, m * n0,  m * n1,  m * n2,  m * n3);
    red_v4(base + 8, m * n4,  m * n5,  m * n6,  1.0f);   // last lane accumulates degree
}

// ---------------------------------------------------------------- layer-1 MLP
__global__ void __launch_bounds__(256)
k_mlp1(const float* __restrict__ W1a, const float* __restrict__ b1a,
       const float* __restrict__ W1b, const float* __restrict__ b1b) {
    __shared__ float sWa[11 * 32], sba[32], sWb[32 * 32], sbb[32];
    for (int i = threadIdx.x; i < 11 * 32; i += blockDim.x) sWa[i] = W1a[i];
    for (int i = threadIdx.x; i < 32 * 32; i += blockDim.x) sWb[i] = W1b[i];
    if (threadIdx.x < 32) { sba[threadIdx.x] = b1a[threadIdx.x]; sbb[threadIdx.x] = b1b[threadIdx.x]; }
    __syncthreads();

    int v = blockIdx.x * blockDim.x + threadIdx.x;
    if (v >= N_NODES) return;
    const float4* ap = g_acc1 + (size_t)v * 4;
    float4 r0 = ap[0], r1 = ap[1], r2 = ap[2];
    float inv = 1.0f / fmaxf(r2.w, 1.0f);   // r2.w = degree
    float x[11] = { r0.x * inv, r0.y * inv, r0.z * inv, r0.w * inv,
                    r1.x * inv, r1.y * inv, r1.z * inv, r1.w * inv,
                    r2.x * inv, r2.y * inv, r2.z * inv };
    float h[32];
#pragma unroll
    for (int j = 0; j < 32; j++) {
        float s = sba[j];
#pragma unroll
        for (int k = 0; k < 11; k++) s += x[k] * sWa[k * 32 + j];
        h[j] = fmaxf(s, 0.f);
    }
    float4* op = g_h1 + (size_t)v * 8;
#pragma unroll
    for (int q = 0; q < 8; q++) {
        float o[4];
#pragma unroll
        for (int jj = 0; jj < 4; jj++) {
            int j = q * 4 + jj;
            float s = sbb[j];
#pragma unroll
            for (int k = 0; k < 32; k++) s += h[k] * sWb[k * 32 + j];
            o[jj] = fmaxf(s, 0.f);
        }
        op[q] = make_float4(o[0], o[1], o[2], o[3]);
    }
}

// ---------------------------------------------------------------- layer-2 edge scatter
__global__ void k_edge2(const float* __restrict__ mask,
                        const int* __restrict__ src, const int* __restrict__ dst, int E) {
    int e = blockIdx.x * blockDim.x + threadIdx.x;
    if (e >= E) return;
    float m = sigmoidf_(__ldg(mask + (e >> 1)));
    int s = src[e];
    int d = dst[e];
    const float4* hp = g_h1 + (size_t)s * 8;
    float* base = (float*)(g_acc2 + (size_t)d * 8);
#pragma unroll
    for (int q = 0; q < 8; q++) {
        float4 h = __ldg(hp + q);
        red_v4(base + q * 4, m * h.x, m * h.y, m * h.z, m * h.w);
    }
}

// ---------------------------------------------------------------- layer-2 MLP + block max
__global__ void __launch_bounds__(256)
k_mlp2max(const float* __restrict__ W2a, const float* __restrict__ b2a,
          const float* __restrict__ W2b, const float* __restrict__ b2b) {
    __shared__ float sWa[32 * 32], sba[32], sWb[32 * 32], sbb[32];
    __shared__ float sred[8 * 32];
    for (int i = threadIdx.x; i < 32 * 32; i += blockDim.x) { sWa[i] = W2a[i]; sWb[i] = W2b[i]; }
    if (threadIdx.x < 32) { sba[threadIdx.x] = b2a[threadIdx.x]; sbb[threadIdx.x] = b2b[threadIdx.x]; }
    __syncthreads();

    float lmax[32];
#pragma unroll
    for (int j = 0; j < 32; j++) lmax[j] = 0.f;

    int stride = gridDim.x * blockDim.x;
    for (int v = blockIdx.x * blockDim.x + threadIdx.x; v < N_NODES; v += stride) {
        float deg = ((const float*)(g_acc1 + (size_t)v * 4))[11];
        float inv = 1.0f / fmaxf(deg, 1.0f);
        const float4* ap = g_acc2 + (size_t)v * 8;
        float x[32];
#pragma unroll
        for (int q = 0; q < 8; q++) {
            float4 r = ap[q];
            x[q * 4 + 0] = r.x * inv; x[q * 4 + 1] = r.y * inv;
            x[q * 4 + 2] = r.z * inv; x[q * 4 + 3] = r.w * inv;
        }
        float h[32];
#pragma unroll
        for (int j = 0; j < 32; j++) {
            float s = sba[j];
#pragma unroll
            for (int k = 0; k < 32; k++) s += x[k] * sWa[k * 32 + j];
            h[j] = fmaxf(s, 0.f);
        }
#pragma unroll
        for (int j = 0; j < 32; j++) {
            float s = sbb[j];
#pragma unroll
            for (int k = 0; k < 32; k++) s += h[k] * sWb[k * 32 + j];
            lmax[j] = fmaxf(lmax[j], fmaxf(s, 0.f));
        }
    }

    // warp butterfly reduce (all lanes end with the warp max vector)
#pragma unroll
    for (int off = 16; off; off >>= 1)
#pragma unroll
        for (int j = 0; j < 32; j++)
            lmax[j] = fmaxf(lmax[j], __shfl_xor_sync(0xFFFFFFFFu, lmax[j], off));

    int warp = threadIdx.x >> 5, lane = threadIdx.x & 31;
    sred[warp * 32 + lane] = lmax[lane];
    __syncthreads();
    if (threadIdx.x < 32) {
        float mv = sred[threadIdx.x];
        int nw = blockDim.x >> 5;
        for (int w = 1; w < nw; w++) mv = fmaxf(mv, sred[w * 32 + threadIdx.x]);
        atomicMax(&g_gmax[threadIdx.x], __float_as_uint(mv));  // valid: all values >= 0
    }
}

// ---------------------------------------------------------------- readout
__global__ void k_final(const float* __restrict__ Wm1, const float* __restrict__ bm1,
                        const float* __restrict__ Wm2, const float* __restrict__ bm2,
                        float* __restrict__ out) {
    __shared__ float sg[32], sh[16];
    int t = threadIdx.x;
    sg[t] = __uint_as_float(g_gmax[t]);
    __syncwarp();
    if (t < 16) {
        float s = bm1[t];
#pragma unroll
        for (int k = 0; k < 32; k++) s += sg[k] * Wm1[k * 16 + t];
        sh[t] = fmaxf(s, 0.f);
    }
    __syncwarp();
    if (t == 0) {
        float l0 = bm2[0], l1 = bm2[1];
#pragma unroll
        for (int k = 0; k < 16; k++) { l0 += sh[k] * Wm2[k * 2 + 0]; l1 += sh[k] * Wm2[k * 2 + 1]; }
        float mx = fmaxf(l0, l1);
        float e0 = __expf(l0 - mx), e1 = __expf(l1 - mx);
        float inv = 1.f / (e0 + e1);
        out[0] = e0 * inv;
        out[1] = e1 * inv;
    }
}

// ---------------------------------------------------------------- launch
extern "C" void kernel_launch(void* const* d_in, const int* in_sizes, int n_in,
                              void* d_out, int out_size) {
    const float* node_feat = (const float*)d_in[0];
    const float* edge_feat = (const float*)d_in[1];
    const float* edge_mask = (const float*)d_in[2];
    const int*   src       = (const int*)  d_in[3];
    const int*   dst       = (const int*)  d_in[4];
    const float* W1a = (const float*)d_in[5];
    const float* b1a = (const float*)d_in[6];
    const float* W1b = (const float*)d_in[7];
    const float* b1b = (const float*)d_in[8];
    const float* W2a = (const float*)d_in[9];
    const float* b2a = (const float*)d_in[10];
    const float* W2b = (const float*)d_in[11];
    const float* b2b = (const float*)d_in[12];
    const float* Wm1 = (const float*)d_in[13];
    const float* bm1 = (const float*)d_in[14];
    const float* Wm2 = (const float*)d_in[15];
    const float* bm2 = (const float*)d_in[16];
    float* out = (float*)d_out;

    int E = in_sizes[3];

    k_init<<<(N_NODES * 8 + 255) / 256, 256>>>();
    k_edge1<<<(E + 255) / 256, 256>>>(node_feat, edge_feat, edge_mask, src, dst, E);
    k_mlp1<<<(N_NODES + 255) / 256, 256>>>(W1a, b1a, W1b, b1b);
    k_edge2<<<(E + 255) / 256, 256>>>(edge_mask, src, dst, E);
    k_mlp2max<<<592, 256>>>(W2a, b2a, W2b, b2b);
    k_final<<<1, 32>>>(Wm1, bm1, Wm2, bm2, out);
}

// round 3
// speedup vs baseline: 1.0934x; 1.0931x over previous
#include <cuda_runtime.h>
#include <cstdint>

#define N_NODES 200000

// Scratch (static __device__ — no allocations allowed)
__device__ float4   g_acc1[N_NODES * 4];   // 16 floats/node: msg[0..10], deg at [11], pad
__device__ float4   g_h1  [N_NODES * 8];   // 32 floats/node
__device__ float4   g_acc2[N_NODES * 8];   // 32 floats/node
__device__ unsigned g_gmax[32];

__device__ __forceinline__ void red_v4(float* p, float a, float b, float c, float d) {
    asm volatile("red.global.add.v4.f32 [%0], {%1,%2,%3,%4};"
                 :: "l"(p), "f"(a), "f"(b), "f"(c), "f"(d) : "memory");
}

__device__ __forceinline__ float sigmoidf_(float x) {
    return 1.0f / (1.0f + __expf(-x));
}

// ---------------------------------------------------------------- init
__global__ void k_init() {
    int i = blockIdx.x * blockDim.x + threadIdx.x;
    float4 z = make_float4(0.f, 0.f, 0.f, 0.f);
    if (i < N_NODES * 4) g_acc1[i] = z;
    if (i < N_NODES * 8) g_acc2[i] = z;
    if (i < 32)          g_gmax[i] = 0u;   // bits of 0.0f; outputs are post-ReLU (>=0)
}

// ---------------------------------------------------------------- layer-1 edge scatter
// 8 lanes cooperate per edge (4 edges per warp).
// msg1 = sigmoid(mask[e/2]) * [edge_feat(4) | node_feat[src](7)], deg in slot 11.
__global__ void __launch_bounds__(256)
k_edge1(const float* __restrict__ nf, const float* __restrict__ ef,
        const float* __restrict__ mask,
        const int* __restrict__ src, const int* __restrict__ dst, int E) {
    const unsigned FULL = 0xFFFFFFFFu;
    int lane = threadIdx.x & 31;
    int warp_global = (blockIdx.x * blockDim.x + threadIdx.x) >> 5;
    int sub = lane >> 3;          // edge slot within warp (0..3)
    int l   = lane & 7;           // lane within edge group
    int g   = lane & 24;          // group base lane
    int e   = warp_global * 4 + sub;
    bool valid = (e < E);

    int s = 0, d = 0;
    float m = 0.f;
    if (valid) {
        s = __ldg(src + e);
        d = __ldg(dst + e);
        m = sigmoidf_(__ldg(mask + (e >> 1)));
    }

    // lanes l<4: edge_feat scalar (coalesced); lanes l<7: node_feat scalar (1 line/edge)
    float efv = (valid && l < 4) ? __ldg(ef + (size_t)e * 4 + l) : 0.f;
    float nfv = (valid && l < 7) ? __ldg(nf + (size_t)s * 7 + l) : 0.f;

    // A_l = v_l for l=0..7 : v0..3 = m*ef, v4..7 = m*nf0..3
    int srcDn = (l >= 4) ? (lane - 4) : lane;
    float nf_dn = __shfl_sync(FULL, nfv, srcDn);
    float A = (l < 4) ? (m * efv) : (m * nf_dn);
    // B_l = v_{8+l} for l=0..3 : v8..10 = m*nf4..6, v11 = deg contribution 1.0
    int srcUp = (l < 3) ? (lane + 4) : lane;
    float nf_up = __shfl_sync(FULL, nfv, srcUp);
    float B = (l == 3) ? 1.0f : (m * nf_up);

    // assemble float4 payloads on lanes 0,1,2 of each group
    int aBase = g + ((l == 1) ? 4 : 0);
    float w0 = __shfl_sync(FULL, A, aBase + 0);
    float w1 = __shfl_sync(FULL, A, aBase + 1);
    float w2 = __shfl_sync(FULL, A, aBase + 2);
    float w3 = __shfl_sync(FULL, A, aBase + 3);
    float u0 = __shfl_sync(FULL, B, g + 0);
    float u1 = __shfl_sync(FULL, B, g + 1);
    float u2 = __shfl_sync(FULL, B, g + 2);
    float u3 = __shfl_sync(FULL, B, g + 3);

    if (valid && l < 3) {
        float* base = (float*)(g_acc1 + (size_t)d * 4);
        if (l == 2) red_v4(base + 8, u0, u1, u2, u3);
        else        red_v4(base + l * 4, w0, w1, w2, w3);
    }
}

// ---------------------------------------------------------------- layer-1 MLP
__global__ void __launch_bounds__(256)
k_mlp1(const float* __restrict__ W1a, const float* __restrict__ b1a,
       const float* __restrict__ W1b, const float* __restrict__ b1b) {
    __shared__ float sWa[11 * 32], sba[32], sWb[32 * 32], sbb[32];
    for (int i = threadIdx.x; i < 11 * 32; i += blockDim.x) sWa[i] = W1a[i];
    for (int i = threadIdx.x; i < 32 * 32; i += blockDim.x) sWb[i] = W1b[i];
    if (threadIdx.x < 32) { sba[threadIdx.x] = b1a[threadIdx.x]; sbb[threadIdx.x] = b1b[threadIdx.x]; }
    __syncthreads();

    int v = blockIdx.x * blockDim.x + threadIdx.x;
    if (v >= N_NODES) return;
    const float4* ap = g_acc1 + (size_t)v * 4;
    float4 r0 = ap[0], r1 = ap[1], r2 = ap[2];
    float inv = 1.0f / fmaxf(r2.w, 1.0f);   // r2.w = degree
    float x[11] = { r0.x * inv, r0.y * inv, r0.z * inv, r0.w * inv,
                    r1.x * inv, r1.y * inv, r1.z * inv, r1.w * inv,
                    r2.x * inv, r2.y * inv, r2.z * inv };
    float h[32];
#pragma unroll
    for (int j = 0; j < 32; j++) {
        float s = sba[j];
#pragma unroll
        for (int k = 0; k < 11; k++) s += x[k] * sWa[k * 32 + j];
        h[j] = fmaxf(s, 0.f);
    }
    float4* op = g_h1 + (size_t)v * 8;
#pragma unroll
    for (int q = 0; q < 8; q++) {
        float o[4];
#pragma unroll
        for (int jj = 0; jj < 4; jj++) {
            int j = q * 4 + jj;
            float s = sbb[j];
#pragma unroll
            for (int k = 0; k < 32; k++) s += h[k] * sWb[k * 32 + j];
            o[jj] = fmaxf(s, 0.f);
        }
        op[q] = make_float4(o[0], o[1], o[2], o[3]);
    }
}

// ---------------------------------------------------------------- layer-2 edge scatter
// 8 lanes per edge: lane l gathers float4 l of h1[src] (one 128B line per edge)
// and issues one red.v4 to float4 l of acc2[dst] (one 128B line per edge).
__global__ void __launch_bounds__(256)
k_edge2(const float* __restrict__ mask,
        const int* __restrict__ src, const int* __restrict__ dst, int E) {
    int lane = threadIdx.x & 31;
    int warp_global = (blockIdx.x * blockDim.x + threadIdx.x) >> 5;
    int sub = lane >> 3;
    int l   = lane & 7;
    int e   = warp_global * 4 + sub;
    if (e >= E) return;

    int s = __ldg(src + e);
    int d = __ldg(dst + e);
    float m = sigmoidf_(__ldg(mask + (e >> 1)));

    float4 h = __ldg(g_h1 + (size_t)s * 8 + l);
    red_v4((float*)(g_acc2 + (size_t)d * 8 + l), m * h.x, m * h.y, m * h.z, m * h.w);
}

// ---------------------------------------------------------------- layer-2 MLP + block max
__global__ void __launch_bounds__(256)
k_mlp2max(const float* __restrict__ W2a, const float* __restrict__ b2a,
          const float* __restrict__ W2b, const float* __restrict__ b2b) {
    __shared__ float sWa[32 * 32], sba[32], sWb[32 * 32], sbb[32];
    __shared__ float sred[8 * 32];
    for (int i = threadIdx.x; i < 32 * 32; i += blockDim.x) { sWa[i] = W2a[i]; sWb[i] = W2b[i]; }
    if (threadIdx.x < 32) { sba[threadIdx.x] = b2a[threadIdx.x]; sbb[threadIdx.x] = b2b[threadIdx.x]; }
    __syncthreads();

    float lmax[32];
#pragma unroll
    for (int j = 0; j < 32; j++) lmax[j] = 0.f;

    int stride = gridDim.x * blockDim.x;
    for (int v = blockIdx.x * blockDim.x + threadIdx.x; v < N_NODES; v += stride) {
        float deg = ((const float*)(g_acc1 + (size_t)v * 4))[11];
        float inv = 1.0f / fmaxf(deg, 1.0f);
        const float4* ap = g_acc2 + (size_t)v * 8;
        float x[32];
#pragma unroll
        for (int q = 0; q < 8; q++) {
            float4 r = ap[q];
            x[q * 4 + 0] = r.x * inv; x[q * 4 + 1] = r.y * inv;
            x[q * 4 + 2] = r.z * inv; x[q * 4 + 3] = r.w * inv;
        }
        float h[32];
#pragma unroll
        for (int j = 0; j < 32; j++) {
            float s = sba[j];
#pragma unroll
            for (int k = 0; k < 32; k++) s += x[k] * sWa[k * 32 + j];
            h[j] = fmaxf(s, 0.f);
        }
#pragma unroll
        for (int j = 0; j < 32; j++) {
            float s = sbb[j];
#pragma unroll
            for (int k = 0; k < 32; k++) s += h[k] * sWb[k * 32 + j];
            lmax[j] = fmaxf(lmax[j], fmaxf(s, 0.f));
        }
    }

    // warp butterfly reduce
#pragma unroll
    for (int off = 16; off; off >>= 1)
#pragma unroll
        for (int j = 0; j < 32; j++)
            lmax[j] = fmaxf(lmax[j], __shfl_xor_sync(0xFFFFFFFFu, lmax[j], off));

    int warp = threadIdx.x >> 5, lane = threadIdx.x & 31;
    sred[warp * 32 + lane] = lmax[lane];
    __syncthreads();
    if (threadIdx.x < 32) {
        float mv = sred[threadIdx.x];
        int nw = blockDim.x >> 5;
        for (int w = 1; w < nw; w++) mv = fmaxf(mv, sred[w * 32 + threadIdx.x]);
        atomicMax(&g_gmax[threadIdx.x], __float_as_uint(mv));  // valid: all values >= 0
    }
}

// ---------------------------------------------------------------- readout
__global__ void k_final(const float* __restrict__ Wm1, const float* __restrict__ bm1,
                        const float* __restrict__ Wm2, const float* __restrict__ bm2,
                        float* __restrict__ out) {
    __shared__ float sg[32], sh[16];
    int t = threadIdx.x;
    sg[t] = __uint_as_float(g_gmax[t]);
    __syncwarp();
    if (t < 16) {
        float s = bm1[t];
#pragma unroll
        for (int k = 0; k < 32; k++) s += sg[k] * Wm1[k * 16 + t];
        sh[t] = fmaxf(s, 0.f);
    }
    __syncwarp();
    if (t == 0) {
        float l0 = bm2[0], l1 = bm2[1];
#pragma unroll
        for (int k = 0; k < 16; k++) { l0 += sh[k] * Wm2[k * 2 + 0]; l1 += sh[k] * Wm2[k * 2 + 1]; }
        float mx = fmaxf(l0, l1);
        float e0 = __expf(l0 - mx), e1 = __expf(l1 - mx);
        float inv = 1.f / (e0 + e1);
        out[0] = e0 * inv;
        out[1] = e1 * inv;
    }
}

// ---------------------------------------------------------------- launch
extern "C" void kernel_launch(void* const* d_in, const int* in_sizes, int n_in,
                              void* d_out, int out_size) {
    const float* node_feat = (const float*)d_in[0];
    const float* edge_feat = (const float*)d_in[1];
    const float* edge_mask = (const float*)d_in[2];
    const int*   src       = (const int*)  d_in[3];
    const int*   dst       = (const int*)  d_in[4];
    const float* W1a = (const float*)d_in[5];
    const float* b1a = (const float*)d_in[6];
    const float* W1b = (const float*)d_in[7];
    const float* b1b = (const float*)d_in[8];
    const float* W2a = (const float*)d_in[9];
    const float* b2a = (const float*)d_in[10];
    const float* W2b = (const float*)d_in[11];
    const float* b2b = (const float*)d_in[12];
    const float* Wm1 = (const float*)d_in[13];
    const float* bm1 = (const float*)d_in[14];
    const float* Wm2 = (const float*)d_in[15];
    const float* bm2 = (const float*)d_in[16];
    float* out = (float*)d_out;

    int E = in_sizes[3];

    // edge kernels: 32 edges per 256-thread block (8 lanes per edge)
    int edge_blocks = (E + 31) / 32;

    k_init<<<(N_NODES * 8 + 255) / 256, 256>>>();
    k_edge1<<<edge_blocks, 256>>>(node_feat, edge_feat, edge_mask, src, dst, E);
    k_mlp1<<<(N_NODES + 255) / 256, 256>>>(W1a, b1a, W1b, b1b);
    k_edge2<<<edge_blocks, 256>>>(edge_mask, src, dst, E);
    k_mlp2max<<<592, 256>>>(W2a, b2a, W2b, b2b);
    k_final<<<1, 32>>>(Wm1, bm1, Wm2, bm2, out);
}

// round 4
// speedup vs baseline: 1.4040x; 1.2841x over previous
#include <cuda_runtime.h>
#include <cstdint>

#define N_NODES 200000

// Scratch (static __device__ — no allocations allowed)
// acc1 row layout (16 floats, PERMUTED, chunk l = lane l's red.v4 payload):
//   [ef0, nf0, nf1, 0 | ef1, nf2, nf3, 0 | ef2, nf4, nf5, 0 | ef3, nf6, deg, 0]
__device__ float4   g_acc1[N_NODES * 4];
__device__ float4   g_nf8 [N_NODES * 2];   // node_feat padded 7 -> 8 floats
__device__ float4   g_h1  [N_NODES * 8];   // 32 floats/node
__device__ float4   g_acc2[N_NODES * 8];   // 32 floats/node
__device__ unsigned g_gmax[32];

__device__ __forceinline__ void red_v4(float* p, float a, float b, float c, float d) {
    asm volatile("red.global.add.v4.f32 [%0], {%1,%2,%3,%4};"
                 :: "l"(p), "f"(a), "f"(b), "f"(c), "f"(d) : "memory");
}

__device__ __forceinline__ float sigmoidf_(float x) {
    return 1.0f / (1.0f + __expf(-x));
}

// ---------------------------------------------------------------- init
__global__ void k_init() {
    int i = blockIdx.x * blockDim.x + threadIdx.x;
    float4 z = make_float4(0.f, 0.f, 0.f, 0.f);
    if (i < N_NODES * 4) g_acc1[i] = z;
    if (i < N_NODES * 8) g_acc2[i] = z;
    if (i < 32)          g_gmax[i] = 0u;   // bits of 0.0f; outputs are post-ReLU (>=0)
}

// ---------------------------------------------------------------- pad node_feat 7 -> 8
__global__ void k_padnf(const float* __restrict__ nf) {
    int v = blockIdx.x * blockDim.x + threadIdx.x;
    if (v >= N_NODES) return;
    const float* p = nf + (size_t)v * 7;
    float4 a = make_float4(__ldg(p + 0), __ldg(p + 1), __ldg(p + 2), __ldg(p + 3));
    float4 b = make_float4(__ldg(p + 4), __ldg(p + 5), __ldg(p + 6), 0.f);
    g_nf8[(size_t)v * 2 + 0] = a;
    g_nf8[(size_t)v * 2 + 1] = b;
}

// ---------------------------------------------------------------- layer-1 edge scatter
// 4 lanes per edge, 2 edges per thread (16 edges/warp). Lane-local payloads, no shuffles.
__global__ void __launch_bounds__(256)
k_edge1(const float* __restrict__ ef, const float* __restrict__ mask,
        const int* __restrict__ src, const int* __restrict__ dst, int E) {
    int lane = threadIdx.x & 31;
    int wg   = (blockIdx.x * blockDim.x + threadIdx.x) >> 5;
    int sub  = lane >> 2;        // 0..7
    int l    = lane & 3;         // 0..3
    int e0   = wg * 16 + sub;
    int e1   = e0 + 8;

    int s0 = 0, d0 = 0, s1 = 0, d1 = 0;
    float m0 = 0.f, m1 = 0.f, ef0 = 0.f, ef1 = 0.f;
    float2 n0 = make_float2(0.f, 0.f), n1 = make_float2(0.f, 0.f);
    bool v0 = (e0 < E), v1 = (e1 < E);

    if (v0) { s0 = __ldg(src + e0); d0 = __ldg(dst + e0); m0 = sigmoidf_(__ldg(mask + (e0 >> 1))); }
    if (v1) { s1 = __ldg(src + e1); d1 = __ldg(dst + e1); m1 = sigmoidf_(__ldg(mask + (e1 >> 1))); }
    if (v0) { ef0 = __ldg(ef + (size_t)e0 * 4 + l); n0 = __ldg(((const float2*)(g_nf8 + (size_t)s0 * 2)) + l); }
    if (v1) { ef1 = __ldg(ef + (size_t)e1 * 4 + l); n1 = __ldg(((const float2*)(g_nf8 + (size_t)s1 * 2)) + l); }

    if (v0) {
        float p2 = (l == 3) ? 1.0f : m0 * n0.y;   // lane 3 slot carries degree
        red_v4((float*)(g_acc1 + (size_t)d0 * 4) + l * 4, m0 * ef0, m0 * n0.x, p2, 0.f);
    }
    if (v1) {
        float p2 = (l == 3) ? 1.0f : m1 * n1.y;
        red_v4((float*)(g_acc1 + (size_t)d1 * 4) + l * 4, m1 * ef1, m1 * n1.x, p2, 0.f);
    }
}

// ---------------------------------------------------------------- layer-1 MLP
// Reads the PERMUTED acc1 layout.
__global__ void __launch_bounds__(256)
k_mlp1(const float* __restrict__ W1a, const float* __restrict__ b1a,
       const float* __restrict__ W1b, const float* __restrict__ b1b) {
    __shared__ float sWa[11 * 32], sba[32], sWb[32 * 32], sbb[32];
    for (int i = threadIdx.x; i < 11 * 32; i += blockDim.x) sWa[i] = W1a[i];
    for (int i = threadIdx.x; i < 32 * 32; i += blockDim.x) sWb[i] = W1b[i];
    if (threadIdx.x < 32) { sba[threadIdx.x] = b1a[threadIdx.x]; sbb[threadIdx.x] = b1b[threadIdx.x]; }
    __syncthreads();

    int v = blockIdx.x * blockDim.x + threadIdx.x;
    if (v >= N_NODES) return;
    const float4* ap = g_acc1 + (size_t)v * 4;
    float4 c0 = ap[0], c1 = ap[1], c2 = ap[2], c3 = ap[3];
    float inv = 1.0f / fmaxf(c3.z, 1.0f);   // deg at chunk3[2]
    // x = [ef0..3, nf0..6] in original order
    float x[11] = { c0.x * inv, c1.x * inv, c2.x * inv, c3.x * inv,
                    c0.y * inv, c0.z * inv, c1.y * inv, c1.z * inv,
                    c2.y * inv, c2.z * inv, c3.y * inv };
    float h[32];
#pragma unroll
    for (int j = 0; j < 32; j++) {
        float s = sba[j];
#pragma unroll
        for (int k = 0; k < 11; k++) s += x[k] * sWa[k * 32 + j];
        h[j] = fmaxf(s, 0.f);
    }
    float4* op = g_h1 + (size_t)v * 8;
#pragma unroll
    for (int q = 0; q < 8; q++) {
        float o[4];
#pragma unroll
        for (int jj = 0; jj < 4; jj++) {
            int j = q * 4 + jj;
            float s = sbb[j];
#pragma unroll
            for (int k = 0; k < 32; k++) s += h[k] * sWb[k * 32 + j];
            o[jj] = fmaxf(s, 0.f);
        }
        op[q] = make_float4(o[0], o[1], o[2], o[3]);
    }
}

// ---------------------------------------------------------------- layer-2 edge scatter
// 8 lanes per edge, 2 edges per thread (8 edges/warp).
__global__ void __launch_bounds__(256)
k_edge2(const float* __restrict__ mask,
        const int* __restrict__ src, const int* __restrict__ dst, int E) {
    int lane = threadIdx.x & 31;
    int wg   = (blockIdx.x * blockDim.x + threadIdx.x) >> 5;
    int sub  = lane >> 3;        // 0..3
    int l    = lane & 7;         // 0..7
    int e0   = wg * 8 + sub;
    int e1   = e0 + 4;

    int s0 = 0, d0 = 0, s1 = 0, d1 = 0;
    float m0 = 0.f, m1 = 0.f;
    bool v0 = (e0 < E), v1 = (e1 < E);
    if (v0) { s0 = __ldg(src + e0); d0 = __ldg(dst + e0); m0 = sigmoidf_(__ldg(mask + (e0 >> 1))); }
    if (v1) { s1 = __ldg(src + e1); d1 = __ldg(dst + e1); m1 = sigmoidf_(__ldg(mask + (e1 >> 1))); }

    float4 h0 = make_float4(0, 0, 0, 0), h1 = make_float4(0, 0, 0, 0);
    if (v0) h0 = __ldg(g_h1 + (size_t)s0 * 8 + l);
    if (v1) h1 = __ldg(g_h1 + (size_t)s1 * 8 + l);

    if (v0) red_v4((float*)(g_acc2 + (size_t)d0 * 8 + l), m0 * h0.x, m0 * h0.y, m0 * h0.z, m0 * h0.w);
    if (v1) red_v4((float*)(g_acc2 + (size_t)d1 * 8 + l), m1 * h1.x, m1 * h1.y, m1 * h1.z, m1 * h1.w);
}

// ---------------------------------------------------------------- layer-2 MLP + block max
__global__ void __launch_bounds__(256)
k_mlp2max(const float* __restrict__ W2a, const float* __restrict__ b2a,
          const float* __restrict__ W2b, const float* __restrict__ b2b) {
    __shared__ float sWa[32 * 32], sba[32], sWb[32 * 32], sbb[32];
    __shared__ float sred[8 * 32];
    for (int i = threadIdx.x; i < 32 * 32; i += blockDim.x) { sWa[i] = W2a[i]; sWb[i] = W2b[i]; }
    if (threadIdx.x < 32) { sba[threadIdx.x] = b2a[threadIdx.x]; sbb[threadIdx.x] = b2b[threadIdx.x]; }
    __syncthreads();

    float lmax[32];
#pragma unroll
    for (int j = 0; j < 32; j++) lmax[j] = 0.f;

    int stride = gridDim.x * blockDim.x;
    for (int v = blockIdx.x * blockDim.x + threadIdx.x; v < N_NODES; v += stride) {
        float deg = ((const float*)(g_acc1 + (size_t)v * 4))[14];  // chunk3[2]
        float inv = 1.0f / fmaxf(deg, 1.0f);
        const float4* ap = g_acc2 + (size_t)v * 8;
        float x[32];
#pragma unroll
        for (int q = 0; q < 8; q++) {
            float4 r = ap[q];
            x[q * 4 + 0] = r.x * inv; x[q * 4 + 1] = r.y * inv;
            x[q * 4 + 2] = r.z * inv; x[q * 4 + 3] = r.w * inv;
        }
        float h[32];
#pragma unroll
        for (int j = 0; j < 32; j++) {
            float s = sba[j];
#pragma unroll
            for (int k = 0; k < 32; k++) s += x[k] * sWa[k * 32 + j];
            h[j] = fmaxf(s, 0.f);
        }
#pragma unroll
        for (int j = 0; j < 32; j++) {
            float s = sbb[j];
#pragma unroll
            for (int k = 0; k < 32; k++) s += h[k] * sWb[k * 32 + j];
            lmax[j] = fmaxf(lmax[j], fmaxf(s, 0.f));
        }
    }

    // warp butterfly reduce
#pragma unroll
    for (int off = 16; off; off >>= 1)
#pragma unroll
        for (int j = 0; j < 32; j++)
            lmax[j] = fmaxf(lmax[j], __shfl_xor_sync(0xFFFFFFFFu, lmax[j], off));

    int warp = threadIdx.x >> 5, lane = threadIdx.x & 31;
    sred[warp * 32 + lane] = lmax[lane];
    __syncthreads();
    if (threadIdx.x < 32) {
        float mv = sred[threadIdx.x];
        int nw = blockDim.x >> 5;
        for (int w = 1; w < nw; w++) mv = fmaxf(mv, sred[w * 32 + threadIdx.x]);
        atomicMax(&g_gmax[threadIdx.x], __float_as_uint(mv));  // valid: all values >= 0
    }
}

// ---------------------------------------------------------------- readout
__global__ void k_final(const float* __restrict__ Wm1, const float* __restrict__ bm1,
                        const float* __restrict__ Wm2, const float* __restrict__ bm2,
                        float* __restrict__ out) {
    __shared__ float sg[32], sh[16];
    int t = threadIdx.x;
    sg[t] = __uint_as_float(g_gmax[t]);
    __syncwarp();
    if (t < 16) {
        float s = bm1[t];
#pragma unroll
        for (int k = 0; k < 32; k++) s += sg[k] * Wm1[k * 16 + t];
        sh[t] = fmaxf(s, 0.f);
    }
    __syncwarp();
    if (t == 0) {
        float l0 = bm2[0], l1 = bm2[1];
#pragma unroll
        for (int k = 0; k < 16; k++) { l0 += sh[k] * Wm2[k * 2 + 0]; l1 += sh[k] * Wm2[k * 2 + 1]; }
        float mx = fmaxf(l0, l1);
        float e0 = __expf(l0 - mx), e1 = __expf(l1 - mx);
        float inv = 1.f / (e0 + e1);
        out[0] = e0 * inv;
        out[1] = e1 * inv;
    }
}

// ---------------------------------------------------------------- launch
extern "C" void kernel_launch(void* const* d_in, const int* in_sizes, int n_in,
                              void* d_out, int out_size) {
    const float* node_feat = (const float*)d_in[0];
    const float* edge_feat = (const float*)d_in[1];
    const float* edge_mask = (const float*)d_in[2];
    const int*   src       = (const int*)  d_in[3];
    const int*   dst       = (const int*)  d_in[4];
    const float* W1a = (const float*)d_in[5];
    const float* b1a = (const float*)d_in[6];
    const float* W1b = (const float*)d_in[7];
    const float* b1b = (const float*)d_in[8];
    const float* W2a = (const float*)d_in[9];
    const float* b2a = (const float*)d_in[10];
    const float* W2b = (const float*)d_in[11];
    const float* b2b = (const float*)d_in[12];
    const float* Wm1 = (const float*)d_in[13];
    const float* bm1 = (const float*)d_in[14];
    const float* Wm2 = (const float*)d_in[15];
    const float* bm2 = (const float*)d_in[16];
    float* out = (float*)d_out;

    int E = in_sizes[3];

    int e1_blocks = (E + 127) / 128;   // 16 edges/warp * 8 warps
    int e2_blocks = (E + 63) / 64;     // 8 edges/warp * 8 warps

    k_init<<<(N_NODES * 8 + 255) / 256, 256>>>();
    k_padnf<<<(N_NODES + 255) / 256, 256>>>(node_feat);
    k_edge1<<<e1_blocks, 256>>>(edge_feat, edge_mask, src, dst, E);
    k_mlp1<<<(N_NODES + 255) / 256, 256>>>(W1a, b1a, W1b, b1b);
    k_edge2<<<e2_blocks, 256>>>(edge_mask, src, dst, E);
    k_mlp2max<<<592, 256>>>(W2a, b2a, W2b, b2b);
    k_final<<<1, 32>>>(Wm1, bm1, Wm2, bm2, out);
}